// round 3
// baseline (speedup 1.0000x reference)
#include <cuda_runtime.h>
#include <cstdint>

#define NG 128
#define HID 16

// ---- physics constants (match reference) ----
__device__ __forceinline__ constexpr float kDT()      { return 0.0001f; }
__device__ __forceinline__ constexpr float kINVDX()   { return 128.0f; }
__device__ __forceinline__ constexpr float kDX()      { return 1.0f / 128.0f; }
__device__ __forceinline__ constexpr float kPVOL()    { return (1.0f/256.0f) * (1.0f/256.0f); }
__device__ __forceinline__ constexpr float kPMASS()   { return (1.0f/256.0f) * (1.0f/256.0f) * 1.0f; }
__device__ __forceinline__ constexpr float kGRAV()    { return 9.8f; }
// -DT * P_VOL * 4 * inv_dx^2  ( = -DT since P_VOL*4*inv_dx^2 == 1 )
__device__ __forceinline__ constexpr float kSTRESS_SCALE() {
    return -0.0001f * ((1.0f/256.0f)*(1.0f/256.0f)) * 4.0f * 128.0f * 128.0f;
}

// ---- scratch (device globals; no allocation allowed) ----
// P2G momentum grid, 8 channels per cell: [vadd0, vadd1, a00, a01, a10, a11, mass, pad]
__device__ float  g_gridP[NG * NG * 8];
// grid velocities after update (only 2 channels needed for G2P)
__device__ float2 g_gridG[NG * NG];

// vectorized global reduction (sm_90+)
__device__ __forceinline__ void red_add_v4(float* addr, float a, float b, float c, float d) {
    asm volatile("red.global.add.v4.f32 [%0], {%1,%2,%3,%4};"
                 :: "l"(__cvta_generic_to_global(addr)), "f"(a), "f"(b), "f"(c), "f"(d)
                 : "memory");
}

// ---------------------------------------------------------------------------
__global__ void k_zero_grid() {
    int i = blockIdx.x * blockDim.x + threadIdx.x;
    float4* p = reinterpret_cast<float4*>(g_gridP);
    if (i < NG * NG * 2) p[i] = make_float4(0.f, 0.f, 0.f, 0.f);
}

// ---------------------------------------------------------------------------
// P2G: F update, MLP stress gradient, scatter to grid; writes x_new, F_new,
// material, Jp to output.
__global__ __launch_bounds__(256) void k_p2g(
    const float* __restrict__ x, const float* __restrict__ v,
    const float* __restrict__ C, const float* __restrict__ F,
    const int*   __restrict__ material, const float* __restrict__ Jp,
    const float* __restrict__ W1, const float* __restrict__ b1,
    const float* __restrict__ W2, const float* __restrict__ b2,
    const float* __restrict__ W3, const float* __restrict__ b3,
    const float* __restrict__ W4, /* b4 unused for grad */
    float* __restrict__ out, int n)
{
    __shared__ float sW1[32], sb1[16];
    __shared__ float sW2[256], sW2T[256], sb2[16];
    __shared__ float sW3[256], sW3T[256], sb3[16];
    __shared__ float sW4[16];

    int t = threadIdx.x;
    if (t < 256) {
        float w2 = W2[t]; sW2[t] = w2; sW2T[(t & 15) * 16 + (t >> 4)] = w2;
        float w3 = W3[t]; sW3[t] = w3; sW3T[(t & 15) * 16 + (t >> 4)] = w3;
    }
    if (t < 32) sW1[t] = W1[t];
    if (t < 16) { sb1[t] = b1[t]; sb2[t] = b2[t]; sb3[t] = b3[t]; sW4[t] = W4[t]; }
    __syncthreads();

    int i = blockIdx.x * blockDim.x + t;
    if (i >= n) return;

    float2 xp = reinterpret_cast<const float2*>(x)[i];
    float2 vp = reinterpret_cast<const float2*>(v)[i];
    float4 Cp = reinterpret_cast<const float4*>(C)[i];  // C00 C01 C10 C11
    float4 Fp = reinterpret_cast<const float4*>(F)[i];  // F00 F01 F10 F11

    // F_new = F + DT * C @ F
    const float DT = kDT();
    float Fn00 = Fp.x + DT * (Cp.x * Fp.x + Cp.y * Fp.z);
    float Fn01 = Fp.y + DT * (Cp.x * Fp.y + Cp.y * Fp.w);
    float Fn10 = Fp.z + DT * (Cp.z * Fp.x + Cp.w * Fp.z);
    float Fn11 = Fp.w + DT * (Cp.z * Fp.y + Cp.w * Fp.w);

    // Cm = F_new^T F_new (symmetric)
    float Cm00 = Fn00 * Fn00 + Fn10 * Fn10;
    float Cm01 = Fn00 * Fn01 + Fn10 * Fn11;
    float Cm11 = Fn01 * Fn01 + Fn11 * Fn11;
    float tr  = Cm00 + Cm11;
    float det = Cm00 * Cm11 - Cm01 * Cm01;
    float gg  = tr * tr - 4.0f * det;
    float gc  = fmaxf(gg, 1e-8f);
    float delta = sqrtf(gc);
    float f0 = 0.5f * (tr + delta);
    float f1 = 0.5f * (tr - delta);

    // ---- MLP forward ----
    float h1[16], h2[16], d3[16];
    #pragma unroll
    for (int k = 0; k < 16; k++) {
        float z = fmaf(sW1[2 * k], f0, fmaf(sW1[2 * k + 1], f1, sb1[k]));
        h1[k] = fmaxf(z, 0.f);
    }
    #pragma unroll
    for (int k = 0; k < 16; k++) {
        float z = sb2[k];
        #pragma unroll
        for (int j = 0; j < 16; j++) z = fmaf(sW2[k * 16 + j], h1[j], z);
        h2[k] = fmaxf(z, 0.f);
    }
    #pragma unroll
    for (int k = 0; k < 16; k++) {
        float z = sb3[k];
        #pragma unroll
        for (int j = 0; j < 16; j++) z = fmaf(sW3[k * 16 + j], h2[j], z);
        d3[k] = (z > 0.f) ? sW4[k] : 0.f;   // relu'(z3) * W4
    }
    // ---- MLP backward ----
    float d2[16];
    #pragma unroll
    for (int j = 0; j < 16; j++) {
        float s = 0.f;
        #pragma unroll
        for (int k = 0; k < 16; k++) s = fmaf(sW3T[j * 16 + k], d3[k], s);
        d2[j] = (h2[j] > 0.f) ? s : 0.f;
    }
    float d1[16];
    #pragma unroll
    for (int j = 0; j < 16; j++) {
        float s = 0.f;
        #pragma unroll
        for (int k = 0; k < 16; k++) s = fmaf(sW2T[j * 16 + k], d2[k], s);
        d1[j] = (h1[j] > 0.f) ? s : 0.f;
    }
    float g0 = 0.f, g1 = 0.f;
    #pragma unroll
    for (int k = 0; k < 16; k++) {
        g0 = fmaf(sW1[2 * k],     d1[k], g0);
        g1 = fmaf(sW1[2 * k + 1], d1[k], g1);
    }

    // chain through eigenvalues: feat = 0.5*(tr +/- delta)
    float hs = 0.5f * (g0 + g1);
    float hd = 0.5f * (g0 - g1);
    float dtr, ddet;
    if (gg > 1e-8f) {
        float inv = 1.0f / delta;
        dtr  = hs + tr * inv * hd;
        ddet = -2.0f * inv * hd;
    } else {
        dtr = hs; ddet = 0.f;
    }
    // G = dpsi/dCm (symmetric); dpsi/dF = 2 * F_new * G
    float G00  = dtr + ddet * Cm11;
    float G11  = dtr + ddet * Cm00;
    float Goff = -ddet * Cm01;
    float P00 = 2.f * (Fn00 * G00  + Fn01 * Goff);
    float P01 = 2.f * (Fn00 * Goff + Fn01 * G11);
    float P10 = 2.f * (Fn10 * G00  + Fn11 * Goff);
    float P11 = 2.f * (Fn10 * Goff + Fn11 * G11);

    const float SS = kSTRESS_SCALE();
    const float PM = kPMASS();
    float a00 = SS * P00 + PM * Cp.x;
    float a01 = SS * P01 + PM * Cp.y;
    float a10 = SS * P10 + PM * Cp.z;
    float a11 = SS * P11 + PM * Cp.w;
    float vadd0 = PM * vp.x - (a00 * xp.x + a01 * xp.y);
    float vadd1 = PM * vp.y - (a10 * xp.x + a11 * xp.y);

    // B-spline weights
    float px = xp.x * kINVDX(), py = xp.y * kINVDX();
    int bx = (int)floorf(px - 0.5f);
    int by = (int)floorf(py - 0.5f);
    float fx = px - (float)bx, fy = py - (float)by;
    float wx[3], wy[3];
    wx[0] = 0.5f * (1.5f - fx) * (1.5f - fx);
    wx[1] = 0.75f - (fx - 1.0f) * (fx - 1.0f);
    wx[2] = 0.5f * (fx - 0.5f) * (fx - 0.5f);
    wy[0] = 0.5f * (1.5f - fy) * (1.5f - fy);
    wy[1] = 0.75f - (fy - 1.0f) * (fy - 1.0f);
    wy[2] = 0.5f * (fy - 0.5f) * (fy - 0.5f);

    #pragma unroll
    for (int ii = 0; ii < 3; ii++) {
        #pragma unroll
        for (int jj = 0; jj < 3; jj++) {
            float wt = wx[ii] * wy[jj];
            float* a = g_gridP + ((bx + ii) * NG + (by + jj)) * 8;
            red_add_v4(a,     wt * vadd0, wt * vadd1, wt * a00, wt * a01);
            red_add_v4(a + 4, wt * a10,   wt * a11,   wt * PM,  0.f);
        }
    }

    // pass-through outputs
    size_t nn = (size_t)n;
    reinterpret_cast<float2*>(out)[i] = make_float2(xp.x + DT * vp.x, xp.y + DT * vp.y);
    reinterpret_cast<float4*>(out + 8 * nn)[i] = make_float4(Fn00, Fn01, Fn10, Fn11);
    out[12 * nn + i] = (float)material[i];
    out[13 * nn + i] = Jp[i];
}

// ---------------------------------------------------------------------------
// Grid update: momentum -> velocity, gravity, boundary clamps.
__global__ void k_grid() {
    int idx = blockIdx.x * blockDim.x + threadIdx.x;
    if (idx >= NG * NG) return;
    int i = idx >> 7;        // row (x)
    int j = idx & (NG - 1);  // col (y)
    const float* g = g_gridP + idx * 8;
    float m  = g[6];
    float gxx = (float)i * kDX();
    float gxy = (float)j * kDX();
    float vx = g[0] + g[2] * gxx + g[3] * gxy;
    float vy = g[1] + g[4] * gxx + g[5] * gxy;
    if (m > 0.f) { vx /= m; vy /= m; }
    vy -= kDT() * kGRAV();
    if (i < 3)      vx = fmaxf(vx, 0.f);
    if (i >= NG-3)  vx = fminf(vx, 0.f);
    if (j < 3)      vy = fmaxf(vy, 0.f);
    if (j >= NG-3)  vy = fminf(vy, 0.f);
    g_gridG[idx] = make_float2(vx, vy);
}

// ---------------------------------------------------------------------------
// G2P: gather new_v; new_C computed cancellation-free as
//   4*inv_dx^2 * sum wt * v_cell (x) (gx_cell - x_p)
__global__ __launch_bounds__(256) void k_g2p(const float* __restrict__ x,
                                             float* __restrict__ out, int n)
{
    int i = blockIdx.x * blockDim.x + threadIdx.x;
    if (i >= n) return;
    float2 xp = reinterpret_cast<const float2*>(x)[i];

    float px = xp.x * kINVDX(), py = xp.y * kINVDX();
    int bx = (int)floorf(px - 0.5f);
    int by = (int)floorf(py - 0.5f);
    float fx = px - (float)bx, fy = py - (float)by;
    float wx[3], wy[3];
    wx[0] = 0.5f * (1.5f - fx) * (1.5f - fx);
    wx[1] = 0.75f - (fx - 1.0f) * (fx - 1.0f);
    wx[2] = 0.5f * (fx - 0.5f) * (fx - 0.5f);
    wy[0] = 0.5f * (1.5f - fy) * (1.5f - fy);
    wy[1] = 0.75f - (fy - 1.0f) * (fy - 1.0f);
    wy[2] = 0.5f * (fy - 0.5f) * (fy - 0.5f);

    float nvx = 0.f, nvy = 0.f;
    float D00 = 0.f, D01 = 0.f, D10 = 0.f, D11 = 0.f;
    #pragma unroll
    for (int ii = 0; ii < 3; ii++) {
        float dxi = (float)(bx + ii) * kDX() - xp.x;
        #pragma unroll
        for (int jj = 0; jj < 3; jj++) {
            float wt = wx[ii] * wy[jj];
            float2 vc = g_gridG[(bx + ii) * NG + (by + jj)];
            float dyj = (float)(by + jj) * kDX() - xp.y;
            float wvx = wt * vc.x, wvy = wt * vc.y;
            nvx += wvx; nvy += wvy;
            D00 = fmaf(wvx, dxi, D00);
            D01 = fmaf(wvx, dyj, D01);
            D10 = fmaf(wvy, dxi, D10);
            D11 = fmaf(wvy, dyj, D11);
        }
    }
    const float S = 4.0f * kINVDX() * kINVDX();  // 65536
    size_t nn = (size_t)n;
    reinterpret_cast<float2*>(out + 2 * nn)[i] = make_float2(nvx, nvy);
    reinterpret_cast<float4*>(out + 4 * nn)[i] =
        make_float4(S * D00, S * D01, S * D10, S * D11);
}

// ---------------------------------------------------------------------------
extern "C" void kernel_launch(void* const* d_in, const int* in_sizes, int n_in,
                              void* d_out, int out_size) {
    const float* x        = (const float*)d_in[0];
    const float* v        = (const float*)d_in[1];
    const float* C        = (const float*)d_in[2];
    const float* F        = (const float*)d_in[3];
    const int*   material = (const int*)  d_in[4];
    const float* Jp       = (const float*)d_in[5];
    // d_in[6] = E, d_in[7] = nu (unused by reference)
    const float* W1 = (const float*)d_in[8];
    const float* b1 = (const float*)d_in[9];
    const float* W2 = (const float*)d_in[10];
    const float* b2 = (const float*)d_in[11];
    const float* W3 = (const float*)d_in[12];
    const float* b3 = (const float*)d_in[13];
    const float* W4 = (const float*)d_in[14];
    float* out = (float*)d_out;

    int n = in_sizes[0] / 2;
    int blocks = (n + 255) / 256;

    k_zero_grid<<<(NG * NG * 2 + 255) / 256, 256>>>();
    k_p2g<<<blocks, 256>>>(x, v, C, F, material, Jp,
                           W1, b1, W2, b2, W3, b3, W4, out, n);
    k_grid<<<NG * NG / 128, 128>>>();
    k_g2p<<<blocks, 256>>>(x, out, n);
}

// round 4
// speedup vs baseline: 1.4102x; 1.4102x over previous
#include <cuda_runtime.h>
#include <cstdint>

#define NG 128
#define HID 16

typedef unsigned long long ull;

// ---- physics constants (match reference) ----
__device__ __forceinline__ constexpr float kDT()    { return 0.0001f; }
__device__ __forceinline__ constexpr float kINVDX() { return 128.0f; }
__device__ __forceinline__ constexpr float kDX()    { return 1.0f / 128.0f; }
__device__ __forceinline__ constexpr float kPMASS() { return (1.0f/256.0f) * (1.0f/256.0f); }
__device__ __forceinline__ constexpr float kGRAV()  { return 9.8f; }
// -DT * P_VOL * 4 * inv_dx^2  ( == -DT since P_VOL*4*inv_dx^2 == 1 )
__device__ __forceinline__ constexpr float kSTRESS_SCALE() {
    return -0.0001f * ((1.0f/256.0f)*(1.0f/256.0f)) * 4.0f * 128.0f * 128.0f;
}

// ---- scratch (device globals; no allocation allowed) ----
// P2G grid, 4 channels per cell: [momx, momy, mass, pad]
__device__ float  g_gridP[NG * NG * 4];
// grid velocities after update
__device__ float2 g_gridG[NG * NG];

// vectorized fire-and-forget global reduction (sm_90+)
__device__ __forceinline__ void red_add_v4(float* addr, float a, float b, float c, float d) {
    asm volatile("red.global.add.v4.f32 [%0], {%1,%2,%3,%4};"
                 :: "l"(__cvta_generic_to_global(addr)), "f"(a), "f"(b), "f"(c), "f"(d)
                 : "memory");
}

// ---- packed f32x2 helpers (Blackwell) ----
__device__ __forceinline__ ull pk2(float a, float b) {
    ull r; asm("mov.b64 %0, {%1,%2};" : "=l"(r) : "f"(a), "f"(b)); return r;
}
__device__ __forceinline__ void upk2(ull p, float& a, float& b) {
    asm("mov.b64 {%0,%1}, %2;" : "=f"(a), "=f"(b) : "l"(p));
}
__device__ __forceinline__ ull fma2(ull a, ull b, ull c) {
    ull d; asm("fma.rn.f32x2 %0, %1, %2, %3;" : "=l"(d) : "l"(a), "l"(b), "l"(c));
    return d;
}

// ---------------------------------------------------------------------------
__global__ void k_zero_grid() {
    int i = blockIdx.x * blockDim.x + threadIdx.x;
    if (i < NG * NG) reinterpret_cast<float4*>(g_gridP)[i] = make_float4(0.f, 0.f, 0.f, 0.f);
}

// ---------------------------------------------------------------------------
// P2G: F update, MLP stress gradient (packed f32x2), scatter momentum+mass.
__global__ __launch_bounds__(256) void k_p2g(
    const float* __restrict__ x, const float* __restrict__ v,
    const float* __restrict__ C, const float* __restrict__ F,
    const int*   __restrict__ material, const float* __restrict__ Jp,
    const float* __restrict__ W1, const float* __restrict__ b1,
    const float* __restrict__ W2, const float* __restrict__ b2,
    const float* __restrict__ W3, const float* __restrict__ b3,
    const float* __restrict__ W4,
    float* __restrict__ out, int n)
{
    // forward packed weights: sWfp[j*8+p] = (W[2p][j], W[2p+1][j])
    __shared__ ull sW2p[128], sW3p[128];
    // backward packed weights = raw W rows reinterpreted: sWr[k*8+p] = (W[k][2p], W[k][2p+1])
    __shared__ ull sW2r[128], sW3r[128];
    __shared__ ull sW1r[16];                    // W1 rows: (W1[k][0], W1[k][1])
    __shared__ ull sC0[8], sC1[8], sB1[8], sB2[8], sB3[8];
    __shared__ float sW4[16];

    int t = threadIdx.x;
    if (t < 128) {
        sW2r[t] = reinterpret_cast<const ull*>(W2)[t];
        sW3r[t] = reinterpret_cast<const ull*>(W3)[t];
        int j = t >> 3, p = t & 7;
        sW2p[t] = pk2(W2[(2*p) * 16 + j], W2[(2*p+1) * 16 + j]);
        sW3p[t] = pk2(W3[(2*p) * 16 + j], W3[(2*p+1) * 16 + j]);
    }
    if (t < 16) { sW1r[t] = reinterpret_cast<const ull*>(W1)[t]; sW4[t] = W4[t]; }
    if (t < 8) {
        sC0[t] = pk2(W1[4*t],     W1[4*t + 2]);
        sC1[t] = pk2(W1[4*t + 1], W1[4*t + 3]);
        sB1[t] = pk2(b1[2*t], b1[2*t + 1]);
        sB2[t] = pk2(b2[2*t], b2[2*t + 1]);
        sB3[t] = pk2(b3[2*t], b3[2*t + 1]);
    }
    __syncthreads();

    int i = blockIdx.x * blockDim.x + t;
    if (i >= n) return;

    float2 xp = reinterpret_cast<const float2*>(x)[i];
    float2 vp = reinterpret_cast<const float2*>(v)[i];
    float4 Cp = reinterpret_cast<const float4*>(C)[i];
    float4 Fp = reinterpret_cast<const float4*>(F)[i];

    // F_new = F + DT * C @ F
    const float DT = kDT();
    float Fn00 = Fp.x + DT * (Cp.x * Fp.x + Cp.y * Fp.z);
    float Fn01 = Fp.y + DT * (Cp.x * Fp.y + Cp.y * Fp.w);
    float Fn10 = Fp.z + DT * (Cp.z * Fp.x + Cp.w * Fp.z);
    float Fn11 = Fp.w + DT * (Cp.z * Fp.y + Cp.w * Fp.w);

    // Cm = F_new^T F_new
    float Cm00 = Fn00 * Fn00 + Fn10 * Fn10;
    float Cm01 = Fn00 * Fn01 + Fn10 * Fn11;
    float Cm11 = Fn01 * Fn01 + Fn11 * Fn11;
    float tr  = Cm00 + Cm11;
    float det = Cm00 * Cm11 - Cm01 * Cm01;
    float gg  = tr * tr - 4.0f * det;
    float delta = sqrtf(fmaxf(gg, 1e-8f));
    float f0 = 0.5f * (tr + delta);
    float f1 = 0.5f * (tr - delta);

    // ---- MLP forward (packed over output-neuron pairs) ----
    ull f0d = pk2(f0, f0), f1d = pk2(f1, f1);
    float h1[16], h2[16], d3[16], d2[16], d1[16];
    ull acc[8];

    #pragma unroll
    for (int p = 0; p < 8; p++) {
        ull z = fma2(sC0[p], f0d, fma2(sC1[p], f1d, sB1[p]));
        float a, b; upk2(z, a, b);
        h1[2*p] = fmaxf(a, 0.f); h1[2*p+1] = fmaxf(b, 0.f);
    }
    #pragma unroll
    for (int p = 0; p < 8; p++) acc[p] = sB2[p];
    #pragma unroll
    for (int j = 0; j < 16; j++) {
        ull hd = pk2(h1[j], h1[j]);
        #pragma unroll
        for (int p = 0; p < 8; p++) acc[p] = fma2(sW2p[j * 8 + p], hd, acc[p]);
    }
    #pragma unroll
    for (int p = 0; p < 8; p++) {
        float a, b; upk2(acc[p], a, b);
        h2[2*p] = fmaxf(a, 0.f); h2[2*p+1] = fmaxf(b, 0.f);
    }
    #pragma unroll
    for (int p = 0; p < 8; p++) acc[p] = sB3[p];
    #pragma unroll
    for (int j = 0; j < 16; j++) {
        ull hd = pk2(h2[j], h2[j]);
        #pragma unroll
        for (int p = 0; p < 8; p++) acc[p] = fma2(sW3p[j * 8 + p], hd, acc[p]);
    }
    #pragma unroll
    for (int p = 0; p < 8; p++) {
        float a, b; upk2(acc[p], a, b);
        d3[2*p]   = (a > 0.f) ? sW4[2*p]   : 0.f;
        d3[2*p+1] = (b > 0.f) ? sW4[2*p+1] : 0.f;
    }

    // ---- MLP backward (packed over pair index p of the output j) ----
    #pragma unroll
    for (int p = 0; p < 8; p++) acc[p] = 0ull;
    #pragma unroll
    for (int k = 0; k < 16; k++) {
        ull dk = pk2(d3[k], d3[k]);
        #pragma unroll
        for (int p = 0; p < 8; p++) acc[p] = fma2(sW3r[k * 8 + p], dk, acc[p]);
    }
    #pragma unroll
    for (int p = 0; p < 8; p++) {
        float a, b; upk2(acc[p], a, b);
        d2[2*p]   = (h2[2*p]   > 0.f) ? a : 0.f;
        d2[2*p+1] = (h2[2*p+1] > 0.f) ? b : 0.f;
    }
    #pragma unroll
    for (int p = 0; p < 8; p++) acc[p] = 0ull;
    #pragma unroll
    for (int k = 0; k < 16; k++) {
        ull dk = pk2(d2[k], d2[k]);
        #pragma unroll
        for (int p = 0; p < 8; p++) acc[p] = fma2(sW2r[k * 8 + p], dk, acc[p]);
    }
    #pragma unroll
    for (int p = 0; p < 8; p++) {
        float a, b; upk2(acc[p], a, b);
        d1[2*p]   = (h1[2*p]   > 0.f) ? a : 0.f;
        d1[2*p+1] = (h1[2*p+1] > 0.f) ? b : 0.f;
    }
    ull gp = 0ull;
    #pragma unroll
    for (int k = 0; k < 16; k++) gp = fma2(sW1r[k], pk2(d1[k], d1[k]), gp);
    float g0, g1; upk2(gp, g0, g1);

    // chain through eigenvalues
    float hs = 0.5f * (g0 + g1);
    float hd = 0.5f * (g0 - g1);
    float dtr, ddet;
    if (gg > 1e-8f) {
        float inv = 1.0f / delta;
        dtr  = hs + tr * inv * hd;
        ddet = -2.0f * inv * hd;
    } else {
        dtr = hs; ddet = 0.f;
    }
    float G00  = dtr + ddet * Cm11;
    float G11  = dtr + ddet * Cm00;
    float Goff = -ddet * Cm01;
    float P00 = 2.f * (Fn00 * G00  + Fn01 * Goff);
    float P01 = 2.f * (Fn00 * Goff + Fn01 * G11);
    float P10 = 2.f * (Fn10 * G00  + Fn11 * Goff);
    float P11 = 2.f * (Fn10 * Goff + Fn11 * G11);

    const float SS = kSTRESS_SCALE();
    const float PM = kPMASS();
    float a00 = SS * P00 + PM * Cp.x;
    float a01 = SS * P01 + PM * Cp.y;
    float a10 = SS * P10 + PM * Cp.z;
    float a11 = SS * P11 + PM * Cp.w;
    float pmvx = PM * vp.x, pmvy = PM * vp.y;

    // B-spline weights
    float px = xp.x * kINVDX(), py = xp.y * kINVDX();
    int bx = (int)floorf(px - 0.5f);
    int by = (int)floorf(py - 0.5f);
    float fx = px - (float)bx, fy = py - (float)by;
    float wx[3], wy[3];
    wx[0] = 0.5f * (1.5f - fx) * (1.5f - fx);
    wx[1] = 0.75f - (fx - 1.0f) * (fx - 1.0f);
    wx[2] = 0.5f * (fx - 0.5f) * (fx - 0.5f);
    wy[0] = 0.5f * (1.5f - fy) * (1.5f - fy);
    wy[1] = 0.75f - (fy - 1.0f) * (fy - 1.0f);
    wy[2] = 0.5f * (fy - 0.5f) * (fy - 0.5f);

    // scatter momentum directly: mom = wt*(pm*v + affine@(gx_cell - x_p)), mass = wt*pm
    #pragma unroll
    for (int ii = 0; ii < 3; ii++) {
        float dgx = (float)(bx + ii) * kDX() - xp.x;
        float m0 = fmaf(a00, dgx, pmvx);
        float m1 = fmaf(a10, dgx, pmvy);
        #pragma unroll
        for (int jj = 0; jj < 3; jj++) {
            float dgy = (float)(by + jj) * kDX() - xp.y;
            float wt = wx[ii] * wy[jj];
            float mx = wt * fmaf(a01, dgy, m0);
            float my = wt * fmaf(a11, dgy, m1);
            float* a = g_gridP + ((bx + ii) * NG + (by + jj)) * 4;
            red_add_v4(a, mx, my, wt * PM, 0.f);
        }
    }

    // pass-through outputs
    size_t nn = (size_t)n;
    reinterpret_cast<float2*>(out)[i] = make_float2(xp.x + DT * vp.x, xp.y + DT * vp.y);
    reinterpret_cast<float4*>(out + 8 * nn)[i] = make_float4(Fn00, Fn01, Fn10, Fn11);
    out[12 * nn + i] = (float)material[i];
    out[13 * nn + i] = Jp[i];
}

// ---------------------------------------------------------------------------
// Grid update: momentum -> velocity, gravity, boundary clamps.
__global__ void k_grid() {
    int idx = blockIdx.x * blockDim.x + threadIdx.x;
    if (idx >= NG * NG) return;
    int i = idx >> 7;
    int j = idx & (NG - 1);
    float4 g = reinterpret_cast<const float4*>(g_gridP)[idx];
    float vx = g.x, vy = g.y, m = g.z;
    if (m > 0.f) { vx /= m; vy /= m; }
    vy -= kDT() * kGRAV();
    if (i < 3)      vx = fmaxf(vx, 0.f);
    if (i >= NG-3)  vx = fminf(vx, 0.f);
    if (j < 3)      vy = fmaxf(vy, 0.f);
    if (j >= NG-3)  vy = fminf(vy, 0.f);
    g_gridG[idx] = make_float2(vx, vy);
}

// ---------------------------------------------------------------------------
// G2P: gather new_v; new_C cancellation-free.
__global__ __launch_bounds__(256) void k_g2p(const float* __restrict__ x,
                                             float* __restrict__ out, int n)
{
    int i = blockIdx.x * blockDim.x + threadIdx.x;
    if (i >= n) return;
    float2 xp = reinterpret_cast<const float2*>(x)[i];

    float px = xp.x * kINVDX(), py = xp.y * kINVDX();
    int bx = (int)floorf(px - 0.5f);
    int by = (int)floorf(py - 0.5f);
    float fx = px - (float)bx, fy = py - (float)by;
    float wx[3], wy[3];
    wx[0] = 0.5f * (1.5f - fx) * (1.5f - fx);
    wx[1] = 0.75f - (fx - 1.0f) * (fx - 1.0f);
    wx[2] = 0.5f * (fx - 0.5f) * (fx - 0.5f);
    wy[0] = 0.5f * (1.5f - fy) * (1.5f - fy);
    wy[1] = 0.75f - (fy - 1.0f) * (fy - 1.0f);
    wy[2] = 0.5f * (fy - 0.5f) * (fy - 0.5f);

    float nvx = 0.f, nvy = 0.f;
    float D00 = 0.f, D01 = 0.f, D10 = 0.f, D11 = 0.f;
    #pragma unroll
    for (int ii = 0; ii < 3; ii++) {
        float dxi = (float)(bx + ii) * kDX() - xp.x;
        #pragma unroll
        for (int jj = 0; jj < 3; jj++) {
            float wt = wx[ii] * wy[jj];
            float2 vc = g_gridG[(bx + ii) * NG + (by + jj)];
            float dyj = (float)(by + jj) * kDX() - xp.y;
            float wvx = wt * vc.x, wvy = wt * vc.y;
            nvx += wvx; nvy += wvy;
            D00 = fmaf(wvx, dxi, D00);
            D01 = fmaf(wvx, dyj, D01);
            D10 = fmaf(wvy, dxi, D10);
            D11 = fmaf(wvy, dyj, D11);
        }
    }
    const float S = 4.0f * kINVDX() * kINVDX();
    size_t nn = (size_t)n;
    reinterpret_cast<float2*>(out + 2 * nn)[i] = make_float2(nvx, nvy);
    reinterpret_cast<float4*>(out + 4 * nn)[i] =
        make_float4(S * D00, S * D01, S * D10, S * D11);
}

// ---------------------------------------------------------------------------
extern "C" void kernel_launch(void* const* d_in, const int* in_sizes, int n_in,
                              void* d_out, int out_size) {
    const float* x        = (const float*)d_in[0];
    const float* v        = (const float*)d_in[1];
    const float* C        = (const float*)d_in[2];
    const float* F        = (const float*)d_in[3];
    const int*   material = (const int*)  d_in[4];
    const float* Jp       = (const float*)d_in[5];
    const float* W1 = (const float*)d_in[8];
    const float* b1 = (const float*)d_in[9];
    const float* W2 = (const float*)d_in[10];
    const float* b2 = (const float*)d_in[11];
    const float* W3 = (const float*)d_in[12];
    const float* b3 = (const float*)d_in[13];
    const float* W4 = (const float*)d_in[14];
    float* out = (float*)d_out;

    int n = in_sizes[0] / 2;
    int blocks = (n + 255) / 256;

    k_zero_grid<<<(NG * NG + 255) / 256, 256>>>();
    k_p2g<<<blocks, 256>>>(x, v, C, F, material, Jp,
                           W1, b1, W2, b2, W3, b3, W4, out, n);
    k_grid<<<NG * NG / 128, 128>>>();
    k_g2p<<<blocks, 256>>>(x, out, n);
}

// round 6
// speedup vs baseline: 1.5091x; 1.0702x over previous
#include <cuda_runtime.h>
#include <cstdint>

#define NG 128
#define HID 16

typedef unsigned long long ull;

// ---- physics constants (match reference) ----
__device__ __forceinline__ constexpr float kDT()    { return 0.0001f; }
__device__ __forceinline__ constexpr float kINVDX() { return 128.0f; }
__device__ __forceinline__ constexpr float kDX()    { return 1.0f / 128.0f; }
__device__ __forceinline__ constexpr float kPMASS() { return (1.0f/256.0f) * (1.0f/256.0f); }
__device__ __forceinline__ constexpr float kGRAV()  { return 9.8f; }
// -DT * P_VOL * 4 * inv_dx^2  ( == -DT since P_VOL*4*inv_dx^2 == 1 )
__device__ __forceinline__ constexpr float kSTRESS_SCALE() {
    return -0.0001f * ((1.0f/256.0f)*(1.0f/256.0f)) * 4.0f * 128.0f * 128.0f;
}

// ---- scratch (device globals; no allocation allowed) ----
// P2G grid, 4 channels per cell: [momx, momy, mass, pad]
__device__ float  g_gridP[NG * NG * 4];
// grid velocities after update
__device__ float2 g_gridG[NG * NG];

// vectorized fire-and-forget global reduction (sm_90+)
__device__ __forceinline__ void red_add_v4(float* addr, float a, float b, float c, float d) {
    asm volatile("red.global.add.v4.f32 [%0], {%1,%2,%3,%4};"
                 :: "l"(__cvta_generic_to_global(addr)), "f"(a), "f"(b), "f"(c), "f"(d)
                 : "memory");
}

// ---- packed f32x2 helpers (Blackwell) ----
__device__ __forceinline__ ull pk2(float a, float b) {
    ull r; asm("mov.b64 %0, {%1,%2};" : "=l"(r) : "f"(a), "f"(b)); return r;
}
__device__ __forceinline__ void upk2(ull p, float& a, float& b) {
    asm("mov.b64 {%0,%1}, %2;" : "=f"(a), "=f"(b) : "l"(p));
}
__device__ __forceinline__ ull fma2(ull a, ull b, ull c) {
    ull d; asm("fma.rn.f32x2 %0, %1, %2, %3;" : "=l"(d) : "l"(a), "l"(b), "l"(c));
    return d;
}

// ---------------------------------------------------------------------------
__global__ void k_zero_grid() {
    int i = blockIdx.x * blockDim.x + threadIdx.x;
    if (i < NG * NG) reinterpret_cast<float4*>(g_gridP)[i] = make_float4(0.f, 0.f, 0.f, 0.f);
}

// ---------------------------------------------------------------------------
// P2G: F update, MLP stress gradient (packed f32x2, 2 particles/thread so each
// shared weight load feeds two FMAs), scatter momentum+mass.
__global__ __launch_bounds__(256) void k_p2g(
    const float* __restrict__ x, const float* __restrict__ v,
    const float* __restrict__ C, const float* __restrict__ F,
    const int*   __restrict__ material, const float* __restrict__ Jp,
    const float* __restrict__ W1, const float* __restrict__ b1,
    const float* __restrict__ W2, const float* __restrict__ b2,
    const float* __restrict__ W3, const float* __restrict__ b3,
    const float* __restrict__ W4,
    float* __restrict__ out, int n)
{
    // forward packed weights: sWxp[j*8+p] = (W[2p][j], W[2p+1][j])
    __shared__ __align__(16) ull sW2p[128], sW3p[128];
    // backward packed weights = raw W rows reinterpreted: sWxr[k*8+p] = (W[k][2p], W[k][2p+1])
    __shared__ __align__(16) ull sW2r[128], sW3r[128];
    __shared__ ull sW1r[16];                    // W1 rows: (W1[k][0], W1[k][1])
    __shared__ ull sC0[8], sC1[8], sB1[8], sB2[8], sB3[8];
    __shared__ float sW4[16];

    int t = threadIdx.x;
    if (t < 128) {
        sW2r[t] = reinterpret_cast<const ull*>(W2)[t];
        sW3r[t] = reinterpret_cast<const ull*>(W3)[t];
        int j = t >> 3, p = t & 7;
        sW2p[t] = pk2(W2[(2*p) * 16 + j], W2[(2*p+1) * 16 + j]);
        sW3p[t] = pk2(W3[(2*p) * 16 + j], W3[(2*p+1) * 16 + j]);
    }
    if (t < 16) { sW1r[t] = reinterpret_cast<const ull*>(W1)[t]; sW4[t] = W4[t]; }
    if (t < 8) {
        sC0[t] = pk2(W1[4*t],     W1[4*t + 2]);
        sC1[t] = pk2(W1[4*t + 1], W1[4*t + 3]);
        sB1[t] = pk2(b1[2*t], b1[2*t + 1]);
        sB2[t] = pk2(b2[2*t], b2[2*t + 1]);
        sB3[t] = pk2(b3[2*t], b3[2*t + 1]);
    }
    __syncthreads();

    int i0 = blockIdx.x * 512 + t;
    if (i0 >= n) return;
    int idx[2] = { i0, i0 + 256 };
    bool val1 = (idx[1] < n);
    int iB = val1 ? idx[1] : i0;   // benign clone if tail

    float2 xp[2], vp[2];
    float4 Cp[2], Fp[2];
    xp[0] = reinterpret_cast<const float2*>(x)[i0];
    vp[0] = reinterpret_cast<const float2*>(v)[i0];
    Cp[0] = reinterpret_cast<const float4*>(C)[i0];
    Fp[0] = reinterpret_cast<const float4*>(F)[i0];
    xp[1] = reinterpret_cast<const float2*>(x)[iB];
    vp[1] = reinterpret_cast<const float2*>(v)[iB];
    Cp[1] = reinterpret_cast<const float4*>(C)[iB];
    Fp[1] = reinterpret_cast<const float4*>(F)[iB];

    const float DT = kDT();
    float Fn00[2], Fn01[2], Fn10[2], Fn11[2];
    float Cm00[2], Cm01[2], Cm11[2], tr[2], gg[2], delta[2];

    #pragma unroll
    for (int u = 0; u < 2; u++) {
        Fn00[u] = Fp[u].x + DT * (Cp[u].x * Fp[u].x + Cp[u].y * Fp[u].z);
        Fn01[u] = Fp[u].y + DT * (Cp[u].x * Fp[u].y + Cp[u].y * Fp[u].w);
        Fn10[u] = Fp[u].z + DT * (Cp[u].z * Fp[u].x + Cp[u].w * Fp[u].z);
        Fn11[u] = Fp[u].w + DT * (Cp[u].z * Fp[u].y + Cp[u].w * Fp[u].w);
        Cm00[u] = Fn00[u] * Fn00[u] + Fn10[u] * Fn10[u];
        Cm01[u] = Fn00[u] * Fn01[u] + Fn10[u] * Fn11[u];
        Cm11[u] = Fn01[u] * Fn01[u] + Fn11[u] * Fn11[u];
        tr[u]  = Cm00[u] + Cm11[u];
        float det = Cm00[u] * Cm11[u] - Cm01[u] * Cm01[u];
        gg[u]  = tr[u] * tr[u] - 4.0f * det;
        delta[u] = sqrtf(fmaxf(gg[u], 1e-8f));
    }

    // ---- MLP forward ----
    float h1[2][16], h2[2][16], d3[2][16];
    ull acc[2][8];

    #pragma unroll
    for (int u = 0; u < 2; u++) {
        float f0 = 0.5f * (tr[u] + delta[u]);
        float f1 = 0.5f * (tr[u] - delta[u]);
        ull f0d = pk2(f0, f0), f1d = pk2(f1, f1);
        #pragma unroll
        for (int p = 0; p < 8; p++) {
            ull z = fma2(sC0[p], f0d, fma2(sC1[p], f1d, sB1[p]));
            float a, b; upk2(z, a, b);
            h1[u][2*p] = fmaxf(a, 0.f); h1[u][2*p+1] = fmaxf(b, 0.f);
        }
    }

    // layer 2 (fused over particles; vector LDS of weights)
    #pragma unroll
    for (int p = 0; p < 8; p++) { acc[0][p] = sB2[p]; acc[1][p] = sB2[p]; }
    #pragma unroll
    for (int j = 0; j < 16; j++) {
        ull hA = pk2(h1[0][j], h1[0][j]);
        ull hB = pk2(h1[1][j], h1[1][j]);
        const ulonglong2* Wv = reinterpret_cast<const ulonglong2*>(sW2p + j * 8);
        #pragma unroll
        for (int q = 0; q < 4; q++) {
            ulonglong2 w = Wv[q];
            acc[0][2*q]   = fma2(w.x, hA, acc[0][2*q]);
            acc[0][2*q+1] = fma2(w.y, hA, acc[0][2*q+1]);
            acc[1][2*q]   = fma2(w.x, hB, acc[1][2*q]);
            acc[1][2*q+1] = fma2(w.y, hB, acc[1][2*q+1]);
        }
    }
    #pragma unroll
    for (int u = 0; u < 2; u++)
        #pragma unroll
        for (int p = 0; p < 8; p++) {
            float a, b; upk2(acc[u][p], a, b);
            h2[u][2*p] = fmaxf(a, 0.f); h2[u][2*p+1] = fmaxf(b, 0.f);
        }

    // layer 3
    #pragma unroll
    for (int p = 0; p < 8; p++) { acc[0][p] = sB3[p]; acc[1][p] = sB3[p]; }
    #pragma unroll
    for (int j = 0; j < 16; j++) {
        ull hA = pk2(h2[0][j], h2[0][j]);
        ull hB = pk2(h2[1][j], h2[1][j]);
        const ulonglong2* Wv = reinterpret_cast<const ulonglong2*>(sW3p + j * 8);
        #pragma unroll
        for (int q = 0; q < 4; q++) {
            ulonglong2 w = Wv[q];
            acc[0][2*q]   = fma2(w.x, hA, acc[0][2*q]);
            acc[0][2*q+1] = fma2(w.y, hA, acc[0][2*q+1]);
            acc[1][2*q]   = fma2(w.x, hB, acc[1][2*q]);
            acc[1][2*q+1] = fma2(w.y, hB, acc[1][2*q+1]);
        }
    }
    #pragma unroll
    for (int u = 0; u < 2; u++)
        #pragma unroll
        for (int p = 0; p < 8; p++) {
            float a, b; upk2(acc[u][p], a, b);
            d3[u][2*p]   = (a > 0.f) ? sW4[2*p]   : 0.f;
            d3[u][2*p+1] = (b > 0.f) ? sW4[2*p+1] : 0.f;
        }

    // ---- MLP backward ----
    #pragma unroll
    for (int p = 0; p < 8; p++) { acc[0][p] = 0ull; acc[1][p] = 0ull; }
    #pragma unroll
    for (int k = 0; k < 16; k++) {
        ull dA = pk2(d3[0][k], d3[0][k]);
        ull dB = pk2(d3[1][k], d3[1][k]);
        const ulonglong2* Wv = reinterpret_cast<const ulonglong2*>(sW3r + k * 8);
        #pragma unroll
        for (int q = 0; q < 4; q++) {
            ulonglong2 w = Wv[q];
            acc[0][2*q]   = fma2(w.x, dA, acc[0][2*q]);
            acc[0][2*q+1] = fma2(w.y, dA, acc[0][2*q+1]);
            acc[1][2*q]   = fma2(w.x, dB, acc[1][2*q]);
            acc[1][2*q+1] = fma2(w.y, dB, acc[1][2*q+1]);
        }
    }
    float d2[2][16];
    #pragma unroll
    for (int u = 0; u < 2; u++)
        #pragma unroll
        for (int p = 0; p < 8; p++) {
            float a, b; upk2(acc[u][p], a, b);
            d2[u][2*p]   = (h2[u][2*p]   > 0.f) ? a : 0.f;
            d2[u][2*p+1] = (h2[u][2*p+1] > 0.f) ? b : 0.f;
        }
    #pragma unroll
    for (int p = 0; p < 8; p++) { acc[0][p] = 0ull; acc[1][p] = 0ull; }
    #pragma unroll
    for (int k = 0; k < 16; k++) {
        ull dA = pk2(d2[0][k], d2[0][k]);
        ull dB = pk2(d2[1][k], d2[1][k]);
        const ulonglong2* Wv = reinterpret_cast<const ulonglong2*>(sW2r + k * 8);
        #pragma unroll
        for (int q = 0; q < 4; q++) {
            ulonglong2 w = Wv[q];
            acc[0][2*q]   = fma2(w.x, dA, acc[0][2*q]);
            acc[0][2*q+1] = fma2(w.y, dA, acc[0][2*q+1]);
            acc[1][2*q]   = fma2(w.x, dB, acc[1][2*q]);
            acc[1][2*q+1] = fma2(w.y, dB, acc[1][2*q+1]);
        }
    }
    ull gp[2] = { 0ull, 0ull };
    #pragma unroll
    for (int k = 0; k < 16; k++) {
        ull w = sW1r[k];
        float aA, bA, aB, bB;
        upk2(acc[0][k >> 1], aA, bA);
        upk2(acc[1][k >> 1], aB, bB);
        float dA = (k & 1) ? bA : aA;
        float dB = (k & 1) ? bB : aB;
        dA = (h1[0][k] > 0.f) ? dA : 0.f;
        dB = (h1[1][k] > 0.f) ? dB : 0.f;
        gp[0] = fma2(w, pk2(dA, dA), gp[0]);
        gp[1] = fma2(w, pk2(dB, dB), gp[1]);
    }

    // ---- chain rule, affine, scatter, outputs (per particle) ----
    size_t nn = (size_t)n;
    #pragma unroll
    for (int u = 0; u < 2; u++) {
        if (u == 1 && !val1) break;
        float g0, g1; upk2(gp[u], g0, g1);
        float hs = 0.5f * (g0 + g1);
        float hd = 0.5f * (g0 - g1);
        float dtr, ddet;
        if (gg[u] > 1e-8f) {
            float inv = 1.0f / delta[u];
            dtr  = hs + tr[u] * inv * hd;
            ddet = -2.0f * inv * hd;
        } else {
            dtr = hs; ddet = 0.f;
        }
        float G00  = dtr + ddet * Cm11[u];
        float G11  = dtr + ddet * Cm00[u];
        float Goff = -ddet * Cm01[u];
        float P00 = 2.f * (Fn00[u] * G00  + Fn01[u] * Goff);
        float P01 = 2.f * (Fn00[u] * Goff + Fn01[u] * G11);
        float P10 = 2.f * (Fn10[u] * G00  + Fn11[u] * Goff);
        float P11 = 2.f * (Fn10[u] * Goff + Fn11[u] * G11);

        const float SS = kSTRESS_SCALE();
        const float PM = kPMASS();
        float a00 = SS * P00 + PM * Cp[u].x;
        float a01 = SS * P01 + PM * Cp[u].y;
        float a10 = SS * P10 + PM * Cp[u].z;
        float a11 = SS * P11 + PM * Cp[u].w;
        float pmvx = PM * vp[u].x, pmvy = PM * vp[u].y;

        float px = xp[u].x * kINVDX(), py = xp[u].y * kINVDX();
        int bx = (int)floorf(px - 0.5f);
        int by = (int)floorf(py - 0.5f);
        float fx = px - (float)bx, fy = py - (float)by;
        float wxx[3], wyy[3];
        wxx[0] = 0.5f * (1.5f - fx) * (1.5f - fx);
        wxx[1] = 0.75f - (fx - 1.0f) * (fx - 1.0f);
        wxx[2] = 0.5f * (fx - 0.5f) * (fx - 0.5f);
        wyy[0] = 0.5f * (1.5f - fy) * (1.5f - fy);
        wyy[1] = 0.75f - (fy - 1.0f) * (fy - 1.0f);
        wyy[2] = 0.5f * (fy - 0.5f) * (fy - 0.5f);

        #pragma unroll
        for (int ii = 0; ii < 3; ii++) {
            float dgx = (float)(bx + ii) * kDX() - xp[u].x;
            float m0 = fmaf(a00, dgx, pmvx);
            float m1 = fmaf(a10, dgx, pmvy);
            #pragma unroll
            for (int jj = 0; jj < 3; jj++) {
                float dgy = (float)(by + jj) * kDX() - xp[u].y;
                float wt = wxx[ii] * wyy[jj];
                float mx = wt * fmaf(a01, dgy, m0);
                float my = wt * fmaf(a11, dgy, m1);
                float* a = g_gridP + ((bx + ii) * NG + (by + jj)) * 4;
                red_add_v4(a, mx, my, wt * PM, 0.f);
            }
        }

        int i = idx[u];
        reinterpret_cast<float2*>(out)[i] =
            make_float2(xp[u].x + DT * vp[u].x, xp[u].y + DT * vp[u].y);
        reinterpret_cast<float4*>(out + 8 * nn)[i] =
            make_float4(Fn00[u], Fn01[u], Fn10[u], Fn11[u]);
        out[12 * nn + i] = (float)material[i];
        out[13 * nn + i] = Jp[i];
    }
}

// ---------------------------------------------------------------------------
// Grid update: momentum -> velocity, gravity, boundary clamps.
__global__ void k_grid() {
    int idx = blockIdx.x * blockDim.x + threadIdx.x;
    if (idx >= NG * NG) return;
    int i = idx >> 7;
    int j = idx & (NG - 1);
    float4 g = reinterpret_cast<const float4*>(g_gridP)[idx];
    float vx = g.x, vy = g.y, m = g.z;
    if (m > 0.f) { vx /= m; vy /= m; }
    vy -= kDT() * kGRAV();
    if (i < 3)      vx = fmaxf(vx, 0.f);
    if (i >= NG-3)  vx = fminf(vx, 0.f);
    if (j < 3)      vy = fmaxf(vy, 0.f);
    if (j >= NG-3)  vy = fminf(vy, 0.f);
    g_gridG[idx] = make_float2(vx, vy);
}

// ---------------------------------------------------------------------------
// G2P: gather new_v; new_C cancellation-free.
__global__ __launch_bounds__(256) void k_g2p(const float* __restrict__ x,
                                             float* __restrict__ out, int n)
{
    int i = blockIdx.x * blockDim.x + threadIdx.x;
    if (i >= n) return;
    float2 xp = reinterpret_cast<const float2*>(x)[i];

    float px = xp.x * kINVDX(), py = xp.y * kINVDX();
    int bx = (int)floorf(px - 0.5f);
    int by = (int)floorf(py - 0.5f);
    float fx = px - (float)bx, fy = py - (float)by;
    float wx[3], wy[3];
    wx[0] = 0.5f * (1.5f - fx) * (1.5f - fx);
    wx[1] = 0.75f - (fx - 1.0f) * (fx - 1.0f);
    wx[2] = 0.5f * (fx - 0.5f) * (fx - 0.5f);
    wy[0] = 0.5f * (1.5f - fy) * (1.5f - fy);
    wy[1] = 0.75f - (fy - 1.0f) * (fy - 1.0f);
    wy[2] = 0.5f * (fy - 0.5f) * (fy - 0.5f);

    float nvx = 0.f, nvy = 0.f;
    float D00 = 0.f, D01 = 0.f, D10 = 0.f, D11 = 0.f;
    #pragma unroll
    for (int ii = 0; ii < 3; ii++) {
        float dxi = (float)(bx + ii) * kDX() - xp.x;
        #pragma unroll
        for (int jj = 0; jj < 3; jj++) {
            float wt = wx[ii] * wy[jj];
            float2 vc = g_gridG[(bx + ii) * NG + (by + jj)];
            float dyj = (float)(by + jj) * kDX() - xp.y;
            float wvx = wt * vc.x, wvy = wt * vc.y;
            nvx += wvx; nvy += wvy;
            D00 = fmaf(wvx, dxi, D00);
            D01 = fmaf(wvx, dyj, D01);
            D10 = fmaf(wvy, dxi, D10);
            D11 = fmaf(wvy, dyj, D11);
        }
    }
    const float S = 4.0f * kINVDX() * kINVDX();
    size_t nn = (size_t)n;
    reinterpret_cast<float2*>(out + 2 * nn)[i] = make_float2(nvx, nvy);
    reinterpret_cast<float4*>(out + 4 * nn)[i] =
        make_float4(S * D00, S * D01, S * D10, S * D11);
}

// ---------------------------------------------------------------------------
extern "C" void kernel_launch(void* const* d_in, const int* in_sizes, int n_in,
                              void* d_out, int out_size) {
    const float* x        = (const float*)d_in[0];
    const float* v        = (const float*)d_in[1];
    const float* C        = (const float*)d_in[2];
    const float* F        = (const float*)d_in[3];
    const int*   material = (const int*)  d_in[4];
    const float* Jp       = (const float*)d_in[5];
    const float* W1 = (const float*)d_in[8];
    const float* b1 = (const float*)d_in[9];
    const float* W2 = (const float*)d_in[10];
    const float* b2 = (const float*)d_in[11];
    const float* W3 = (const float*)d_in[12];
    const float* b3 = (const float*)d_in[13];
    const float* W4 = (const float*)d_in[14];
    float* out = (float*)d_out;

    int n = in_sizes[0] / 2;

    k_zero_grid<<<(NG * NG + 255) / 256, 256>>>();
    k_p2g<<<(n + 511) / 512, 256>>>(x, v, C, F, material, Jp,
                                    W1, b1, W2, b2, W3, b3, W4, out, n);
    k_grid<<<NG * NG / 128, 128>>>();
    k_g2p<<<(n + 255) / 256, 256>>>(x, out, n);
}